// round 4
// baseline (speedup 1.0000x reference)
#include <cuda_runtime.h>
#include <math.h>

// EnsembleSurrogate: 16 MLPs (32 -> 64 -> 64 -> 64 -> 8), batch 131072.
// Output: [mean(131072x8); std_ddof1(131072x8)] as float32.
//
// Two-kernel plan to kill wave quantization:
//   Kernel 1 (grid 2048, TPB 128): CTA (tile, half) computes 8 of the 16
//     models for its 128-sample tile and writes partial (sum, sumsq)[8] per
//     sample to a __device__ scratch. Work granule = tile x 8 models ->
//     2048 granules over 296 CTA slots -> +1.2% quantization (vs +15.6%).
//   Kernel 2: combines the two partials into mean / unbiased std.
//
// Compute core (unchanged from prior round): one sample per thread; per
// model, weights staged into smem (warp-uniform LDS -> broadcast); x lives
// in 32 registers for the whole kernel; ONE thread-private-column hidden
// buffer overwritten in place (no inter-layer syncs); packed f32x2 FFMA2
// (PTX fma.rn.f32x2, exact fp32 pair math); layer 4 fused off layer-3
// register accumulators.

#define TPB 128

constexpr int BATCH    = 131072;
constexpr int IN_DIM   = 32;
constexpr int HID      = 64;
constexpr int OUT_DIM  = 8;
constexpr int N_MODELS = 16;
constexpr int M_HALF   = N_MODELS / 2;   // models per CTA

// Shared memory layout (floats)
constexpr int H_FLOATS = HID * TPB;              // 64*128 = 8192 (one buffer)

// Weight buffer offsets (floats); every offset is a multiple of 4 so that
// float4 / ulonglong2 accesses are 16B aligned.
constexpr int OFF_W1 = 0;
constexpr int OFF_B1 = OFF_W1 + IN_DIM * HID;    // 2048
constexpr int OFF_W2 = OFF_B1 + HID;             // 2112
constexpr int OFF_B2 = OFF_W2 + HID * HID;       // 6208
constexpr int OFF_W3 = OFF_B2 + HID;             // 6272
constexpr int OFF_B3 = OFF_W3 + HID * HID;       // 10368
constexpr int OFF_W4 = OFF_B3 + HID;             // 10432
constexpr int OFF_B4 = OFF_W4 + HID * OUT_DIM;   // 10944
constexpr int W_FLOATS = OFF_B4 + OUT_DIM;       // 10952

constexpr int SMEM_FLOATS = H_FLOATS + W_FLOATS; // 19144
constexpr int SMEM_BYTES  = SMEM_FLOATS * 4;     // 76576 B  (2 CTAs/SM)

// Scratch: [half][sample][16] = (sum[8], sq[8]) per half-ensemble per sample.
__device__ float g_part[2ull * BATCH * 16];      // 16.8 MB, module-static

// ---- packed f32x2 helpers (exact fp32 pair math; SASS: FFMA2 / FADD2) ----
#define FMA_X2(d, a, b) \
    asm("fma.rn.f32x2 %0, %1, %2, %0;" : "+l"(d) : "l"(a), "l"(b))
#define ADD_X2(d, a) \
    asm("add.rn.f32x2 %0, %0, %1;" : "+l"(d) : "l"(a))
#define DUP_X2(d, s) \
    asm("mov.b64 %0, {%1, %1};" : "=l"(d) : "f"(s))
#define UNPACK_X2(lo, hi, v) \
    asm("mov.b64 {%0, %1}, %2;" : "=f"(lo), "=f"(hi) : "l"(v))

__global__ __launch_bounds__(TPB, 2)
void ensemble_half_kernel(const float* __restrict__ x,
                          const float* __restrict__ W1, const float* __restrict__ b1,
                          const float* __restrict__ W2, const float* __restrict__ b2,
                          const float* __restrict__ W3, const float* __restrict__ b3,
                          const float* __restrict__ W4, const float* __restrict__ b4)
{
    extern __shared__ float sm[];
    float* hs = sm;                       // [HID][TPB] hidden, in-place reuse
    float* wb = sm + H_FLOATS;            // model weights

    const int tid  = threadIdx.x;
    const int half = blockIdx.x & 1;      // which 8-model half
    const int tile = blockIdx.x >> 1;     // which 128-sample tile
    const int b    = tile * TPB + tid;
    const int m0   = half * M_HALF;

    // ---- Load this thread's input row into registers (persists all models).
    float xr[IN_DIM];
    {
        const float4* xg = (const float4*)(x + (size_t)b * IN_DIM);
        #pragma unroll
        for (int i = 0; i < IN_DIM / 4; i++) {
            float4 v = xg[i];
            xr[4*i+0] = v.x; xr[4*i+1] = v.y; xr[4*i+2] = v.z; xr[4*i+3] = v.w;
        }
    }

    unsigned long long sum2[OUT_DIM / 2], sq2[OUT_DIM / 2];
    #pragma unroll
    for (int o = 0; o < OUT_DIM / 2; o++) { sum2[o] = 0ull; sq2[o] = 0ull; }

    for (int mi = 0; mi < M_HALF; mi++) {
        const int m = m0 + mi;
        __syncthreads();  // previous model's readers of wb are done

        // ---- Stage model m weights into smem (vectorized) ----
        {
            float4* d = (float4*)wb;
            const float4* s1 = (const float4*)(W1 + (size_t)m * IN_DIM * HID);
            #pragma unroll
            for (int i = 0; i < (IN_DIM * HID) / 4 / TPB; i++)
                d[OFF_W1/4 + tid + i * TPB] = s1[tid + i * TPB];
            const float4* s2 = (const float4*)(W2 + (size_t)m * HID * HID);
            #pragma unroll
            for (int i = 0; i < (HID * HID) / 4 / TPB; i++)
                d[OFF_W2/4 + tid + i * TPB] = s2[tid + i * TPB];
            const float4* s3 = (const float4*)(W3 + (size_t)m * HID * HID);
            #pragma unroll
            for (int i = 0; i < (HID * HID) / 4 / TPB; i++)
                d[OFF_W3/4 + tid + i * TPB] = s3[tid + i * TPB];
            const float4* s4 = (const float4*)(W4 + (size_t)m * HID * OUT_DIM);
            if (tid < (HID * OUT_DIM) / 4)
                d[OFF_W4/4 + tid] = s4[tid];
            const float4* t1 = (const float4*)(b1 + (size_t)m * HID);
            if (tid < HID / 4) d[OFF_B1/4 + tid] = t1[tid];
            const float4* t2 = (const float4*)(b2 + (size_t)m * HID);
            if (tid < HID / 4) d[OFF_B2/4 + tid] = t2[tid];
            const float4* t3 = (const float4*)(b3 + (size_t)m * HID);
            if (tid < HID / 4) d[OFF_B3/4 + tid] = t3[tid];
            const float4* t4 = (const float4*)(b4 + (size_t)m * OUT_DIM);
            if (tid < OUT_DIM / 4) d[OFF_B4/4 + tid] = t4[tid];
        }
        __syncthreads();

        unsigned long long acc2[HID / 2];   // 32 packed fp32 pairs

        // ---- Layer 1: xr(regs,32) -> h(64), relu -> hs ----
        {
            const unsigned long long* bb = (const unsigned long long*)(wb + OFF_B1);
            #pragma unroll
            for (int j = 0; j < HID / 2; j++) acc2[j] = bb[j];
            #pragma unroll
            for (int k = 0; k < IN_DIM; k++) {
                unsigned long long a2; DUP_X2(a2, xr[k]);
                const ulonglong2* wr = (const ulonglong2*)(wb + OFF_W1 + k * HID);
                #pragma unroll
                for (int q = 0; q < HID / 4; q++) {   // 16 LDS.128
                    ulonglong2 w = wr[q];
                    FMA_X2(acc2[2*q+0], a2, w.x);
                    FMA_X2(acc2[2*q+1], a2, w.y);
                }
            }
            #pragma unroll
            for (int j = 0; j < HID / 2; j++) {
                float lo, hi; UNPACK_X2(lo, hi, acc2[j]);
                hs[(2*j  ) * TPB + tid] = fmaxf(lo, 0.f);
                hs[(2*j+1) * TPB + tid] = fmaxf(hi, 0.f);
            }
        }
        // no sync: each thread owns its own column of hs

        // ---- Layer 2: hs -> h(64), relu -> hs (in place after full read) ----
        {
            const unsigned long long* bb = (const unsigned long long*)(wb + OFF_B2);
            #pragma unroll
            for (int j = 0; j < HID / 2; j++) acc2[j] = bb[j];
            #pragma unroll 2
            for (int k = 0; k < HID; k++) {
                float a = hs[k * TPB + tid];
                unsigned long long a2; DUP_X2(a2, a);
                const ulonglong2* wr = (const ulonglong2*)(wb + OFF_W2 + k * HID);
                #pragma unroll
                for (int q = 0; q < HID / 4; q++) {
                    ulonglong2 w = wr[q];
                    FMA_X2(acc2[2*q+0], a2, w.x);
                    FMA_X2(acc2[2*q+1], a2, w.y);
                }
            }
            // all reads of this thread's column are complete -> safe overwrite
            #pragma unroll
            for (int j = 0; j < HID / 2; j++) {
                float lo, hi; UNPACK_X2(lo, hi, acc2[j]);
                hs[(2*j  ) * TPB + tid] = fmaxf(lo, 0.f);
                hs[(2*j+1) * TPB + tid] = fmaxf(hi, 0.f);
            }
        }

        // ---- Layer 3: hs -> acc2 (kept in registers) ----
        {
            const unsigned long long* bb = (const unsigned long long*)(wb + OFF_B3);
            #pragma unroll
            for (int j = 0; j < HID / 2; j++) acc2[j] = bb[j];
            #pragma unroll 2
            for (int k = 0; k < HID; k++) {
                float a = hs[k * TPB + tid];
                unsigned long long a2; DUP_X2(a2, a);
                const ulonglong2* wr = (const ulonglong2*)(wb + OFF_W3 + k * HID);
                #pragma unroll
                for (int q = 0; q < HID / 4; q++) {
                    ulonglong2 w = wr[q];
                    FMA_X2(acc2[2*q+0], a2, w.x);
                    FMA_X2(acc2[2*q+1], a2, w.y);
                }
            }
        }

        // ---- Layer 4 fused: relu(acc2) -> preds(8); accumulate sum/sumsq ----
        {
            unsigned long long o2[OUT_DIM / 2];
            const unsigned long long* bb = (const unsigned long long*)(wb + OFF_B4);
            #pragma unroll
            for (int oi = 0; oi < OUT_DIM / 2; oi++) o2[oi] = bb[oi];
            #pragma unroll 4
            for (int k2 = 0; k2 < HID / 2; k2++) {
                float lo, hi; UNPACK_X2(lo, hi, acc2[k2]);
                lo = fmaxf(lo, 0.f);
                hi = fmaxf(hi, 0.f);
                unsigned long long alo2, ahi2;
                DUP_X2(alo2, lo);
                DUP_X2(ahi2, hi);
                // rows k=2*k2 and k=2*k2+1: 16 floats = 4 ulonglong2
                const ulonglong2* wr = (const ulonglong2*)(wb + OFF_W4 + (2 * k2) * OUT_DIM);
                ulonglong2 wa = wr[0], wc = wr[1];   // row k
                ulonglong2 we = wr[2], wg = wr[3];   // row k+1
                FMA_X2(o2[0], alo2, wa.x);
                FMA_X2(o2[1], alo2, wa.y);
                FMA_X2(o2[2], alo2, wc.x);
                FMA_X2(o2[3], alo2, wc.y);
                FMA_X2(o2[0], ahi2, we.x);
                FMA_X2(o2[1], ahi2, we.y);
                FMA_X2(o2[2], ahi2, wg.x);
                FMA_X2(o2[3], ahi2, wg.y);
            }
            #pragma unroll
            for (int oi = 0; oi < OUT_DIM / 2; oi++) {
                ADD_X2(sum2[oi], o2[oi]);
                FMA_X2(sq2[oi], o2[oi], o2[oi]);
            }
        }
    }

    // ---- Write partial (sum[8], sq[8]) for this half ----
    {
        float s[OUT_DIM], q[OUT_DIM];
        #pragma unroll
        for (int oi = 0; oi < OUT_DIM / 2; oi++) {
            UNPACK_X2(s[2*oi], s[2*oi+1], sum2[oi]);
            UNPACK_X2(q[2*oi], q[2*oi+1], sq2[oi]);
        }
        float4* pw = (float4*)(g_part + ((size_t)half * BATCH + b) * 16);
        pw[0] = make_float4(s[0], s[1], s[2], s[3]);
        pw[1] = make_float4(s[4], s[5], s[6], s[7]);
        pw[2] = make_float4(q[0], q[1], q[2], q[3]);
        pw[3] = make_float4(q[4], q[5], q[6], q[7]);
    }
}

// ---- Kernel 2: combine the two half-ensemble partials into mean / std ----
#define CTPB 256

__global__ __launch_bounds__(CTPB)
void combine_kernel(float* __restrict__ out)
{
    const int b = blockIdx.x * CTPB + threadIdx.x;   // sample index

    const float4* pa = (const float4*)(g_part + (size_t)b * 16);
    const float4* pb = (const float4*)(g_part + ((size_t)BATCH + b) * 16);
    float4 sa0 = pa[0], sa1 = pa[1], qa0 = pa[2], qa1 = pa[3];
    float4 sb0 = pb[0], sb1 = pb[1], qb0 = pb[2], qb1 = pb[3];

    float s[OUT_DIM] = { sa0.x + sb0.x, sa0.y + sb0.y, sa0.z + sb0.z, sa0.w + sb0.w,
                         sa1.x + sb1.x, sa1.y + sb1.y, sa1.z + sb1.z, sa1.w + sb1.w };
    float q[OUT_DIM] = { qa0.x + qb0.x, qa0.y + qb0.y, qa0.z + qb0.z, qa0.w + qb0.w,
                         qa1.x + qb1.x, qa1.y + qb1.y, qa1.z + qb1.z, qa1.w + qb1.w };

    float mean[OUT_DIM], stdv[OUT_DIM];
    #pragma unroll
    for (int oi = 0; oi < OUT_DIM; oi++) {
        mean[oi] = s[oi] * (1.0f / N_MODELS);
        float var = (q[oi] - s[oi] * s[oi] * (1.0f / N_MODELS)) * (1.0f / (N_MODELS - 1));
        stdv[oi] = sqrtf(fmaxf(var, 0.f));
    }

    float4* om = (float4*)(out + (size_t)b * OUT_DIM);
    float4* os = (float4*)(out + (size_t)BATCH * OUT_DIM + (size_t)b * OUT_DIM);
    om[0] = make_float4(mean[0], mean[1], mean[2], mean[3]);
    om[1] = make_float4(mean[4], mean[5], mean[6], mean[7]);
    os[0] = make_float4(stdv[0], stdv[1], stdv[2], stdv[3]);
    os[1] = make_float4(stdv[4], stdv[5], stdv[6], stdv[7]);
}

extern "C" void kernel_launch(void* const* d_in, const int* in_sizes, int n_in,
                              void* d_out, int out_size)
{
    const float* x  = (const float*)d_in[0];
    const float* W1 = (const float*)d_in[1];
    const float* b1 = (const float*)d_in[2];
    const float* W2 = (const float*)d_in[3];
    const float* b2 = (const float*)d_in[4];
    const float* W3 = (const float*)d_in[5];
    const float* b3 = (const float*)d_in[6];
    const float* W4 = (const float*)d_in[7];
    const float* b4 = (const float*)d_in[8];
    float* out = (float*)d_out;

    cudaFuncSetAttribute(ensemble_half_kernel,
                         cudaFuncAttributeMaxDynamicSharedMemorySize, SMEM_BYTES);

    ensemble_half_kernel<<<(BATCH / TPB) * 2, TPB, SMEM_BYTES>>>(
        x, W1, b1, W2, b2, W3, b3, W4, b4);
    combine_kernel<<<BATCH / CTPB, CTPB>>>(out);
}

// round 17
// speedup vs baseline: 1.3225x; 1.3225x over previous
#include <cuda_runtime.h>
#include <math.h>

// EnsembleSurrogate: 16 MLPs (32 -> 64 -> 64 -> 64 -> 8), batch 131072.
// Output: [mean(131072x8); std_ddof1(131072x8)] as float32.
//
// Main kernel: grid 2048 = 512 tiles (256 samples) x 4 model-quarters.
// TWO samples per thread (interleaved smem columns 2*tid, 2*tid+1) so every
// weight LDS.128 feeds 4 FFMA2 (2 per sample) -> LDS-per-MAC halved vs the
// 1-sample/thread variant (attacks the smem-crossbar/issue bound).
// Weights staged in smem (warp-uniform LDS -> broadcast); ONE in-place
// hidden buffer (thread-private column pair -> no inter-layer syncs);
// packed f32x2 FFMA2 math (exact fp32); layer 4 fused off layer-3 register
// accumulators; per-quarter (sum, sumsq)[8] partials to __device__ scratch.
//
// Launch sequence has period 5 (main + 4 quarter-combines) so ncu -s 5 -c 1
// captures the MAIN kernel (launch idx 5 = first launch of 2nd call).

#define TPB 128
#define TPW 256   // samples per tile = smem row width

constexpr int BATCH    = 131072;
constexpr int IN_DIM   = 32;
constexpr int HID      = 64;
constexpr int OUT_DIM  = 8;
constexpr int N_MODELS = 16;
constexpr int M_QUART  = N_MODELS / 4;   // 4 models per CTA
constexpr int N_TILES  = BATCH / TPW;    // 512

// Shared memory layout (floats)
constexpr int H_FLOATS = HID * TPW;              // 64*256 = 16384 (64KB)

constexpr int OFF_W1 = 0;
constexpr int OFF_B1 = OFF_W1 + IN_DIM * HID;    // 2048
constexpr int OFF_W2 = OFF_B1 + HID;             // 2112
constexpr int OFF_B2 = OFF_W2 + HID * HID;       // 6208
constexpr int OFF_W3 = OFF_B2 + HID;             // 6272
constexpr int OFF_B3 = OFF_W3 + HID * HID;       // 10368
constexpr int OFF_W4 = OFF_B3 + HID;             // 10432
constexpr int OFF_B4 = OFF_W4 + HID * OUT_DIM;   // 10944
constexpr int W_FLOATS = OFF_B4 + OUT_DIM;       // 10952

constexpr int SMEM_FLOATS = H_FLOATS + W_FLOATS; // 27336
constexpr int SMEM_BYTES  = SMEM_FLOATS * 4;     // 109344 B (2 CTAs/SM)

// Scratch: [quarter][sample][16] = (sum[8], sq[8]).
__device__ float g_part[4ull * BATCH * 16];      // 33.5 MB

// ---- packed f32x2 helpers (exact fp32 pair math) ----
#define FMA_X2(d, a, b) \
    asm("fma.rn.f32x2 %0, %1, %2, %0;" : "+l"(d) : "l"(a), "l"(b))
#define ADD_X2(d, a) \
    asm("add.rn.f32x2 %0, %0, %1;" : "+l"(d) : "l"(a))
#define DUP_X2(d, s) \
    asm("mov.b64 %0, {%1, %1};" : "=l"(d) : "f"(s))
#define PACK_X2(d, lo, hi) \
    asm("mov.b64 %0, {%1, %2};" : "=l"(d) : "f"(lo), "f"(hi))
#define UNPACK_X2(lo, hi, v) \
    asm("mov.b64 {%0, %1}, %2;" : "=f"(lo), "=f"(hi) : "l"(v))

__global__ __launch_bounds__(TPB, 2)
void ensemble_quarter_kernel(const float* __restrict__ x,
                             const float* __restrict__ W1, const float* __restrict__ b1,
                             const float* __restrict__ W2, const float* __restrict__ b2,
                             const float* __restrict__ W3, const float* __restrict__ b3,
                             const float* __restrict__ W4, const float* __restrict__ b4)
{
    extern __shared__ float sm[];
    float* hs = sm;                       // [HID][TPW] hidden, in-place reuse
    float* wb = sm + H_FLOATS;            // model weights

    const int tid   = threadIdx.x;
    const int quart = blockIdx.x & 3;     // which 4-model quarter
    const int tile  = blockIdx.x >> 2;    // which 256-sample tile
    const int b0    = tile * TPW + 2 * tid;   // sample A (B = b0 + 1)
    const int m0    = quart * M_QUART;
    const int col   = 2 * tid;            // this thread's smem column pair

    unsigned long long sum2a[OUT_DIM/2], sq2a[OUT_DIM/2];
    unsigned long long sum2b[OUT_DIM/2], sq2b[OUT_DIM/2];
    #pragma unroll
    for (int o = 0; o < OUT_DIM / 2; o++) {
        sum2a[o] = 0ull; sq2a[o] = 0ull; sum2b[o] = 0ull; sq2b[o] = 0ull;
    }

    const float4* xga = (const float4*)(x + (size_t)b0 * IN_DIM);        // 8 x float4
    const float4* xgb = (const float4*)(x + (size_t)(b0 + 1) * IN_DIM);  // 8 x float4

    for (int mi = 0; mi < M_QUART; mi++) {
        const int m = m0 + mi;
        __syncthreads();  // previous model's readers of wb are done

        // ---- Stage model m weights into smem (vectorized) ----
        {
            float4* d = (float4*)wb;
            const float4* s1 = (const float4*)(W1 + (size_t)m * IN_DIM * HID);
            #pragma unroll
            for (int i = 0; i < (IN_DIM * HID) / 4 / TPB; i++)
                d[OFF_W1/4 + tid + i * TPB] = s1[tid + i * TPB];
            const float4* s2 = (const float4*)(W2 + (size_t)m * HID * HID);
            #pragma unroll
            for (int i = 0; i < (HID * HID) / 4 / TPB; i++)
                d[OFF_W2/4 + tid + i * TPB] = s2[tid + i * TPB];
            const float4* s3 = (const float4*)(W3 + (size_t)m * HID * HID);
            #pragma unroll
            for (int i = 0; i < (HID * HID) / 4 / TPB; i++)
                d[OFF_W3/4 + tid + i * TPB] = s3[tid + i * TPB];
            const float4* s4 = (const float4*)(W4 + (size_t)m * HID * OUT_DIM);
            if (tid < (HID * OUT_DIM) / 4)
                d[OFF_W4/4 + tid] = s4[tid];
            const float4* t1 = (const float4*)(b1 + (size_t)m * HID);
            if (tid < HID / 4) d[OFF_B1/4 + tid] = t1[tid];
            const float4* t2 = (const float4*)(b2 + (size_t)m * HID);
            if (tid < HID / 4) d[OFF_B2/4 + tid] = t2[tid];
            const float4* t3 = (const float4*)(b3 + (size_t)m * HID);
            if (tid < HID / 4) d[OFF_B3/4 + tid] = t3[tid];
            const float4* t4 = (const float4*)(b4 + (size_t)m * OUT_DIM);
            if (tid < OUT_DIM / 4) d[OFF_B4/4 + tid] = t4[tid];
        }
        __syncthreads();

        unsigned long long acc2a[HID/2], acc2b[HID/2];  // 32+32 packed pairs

        // ---- Layer 1: x(global, L2-hot) -> h(64), relu -> hs ----
        {
            const unsigned long long* bb = (const unsigned long long*)(wb + OFF_B1);
            #pragma unroll
            for (int j = 0; j < HID / 2; j++) { acc2a[j] = bb[j]; acc2b[j] = bb[j]; }
            #pragma unroll
            for (int c = 0; c < IN_DIM / 4; c++) {     // 8 chunks of 4 k's
                float4 xa = xga[c];
                float4 xb = xgb[c];
                #pragma unroll
                for (int kk = 0; kk < 4; kk++) {
                    float va = (kk == 0) ? xa.x : (kk == 1) ? xa.y : (kk == 2) ? xa.z : xa.w;
                    float vb = (kk == 0) ? xb.x : (kk == 1) ? xb.y : (kk == 2) ? xb.z : xb.w;
                    unsigned long long a2, bb2;
                    DUP_X2(a2, va);
                    DUP_X2(bb2, vb);
                    const ulonglong2* wr =
                        (const ulonglong2*)(wb + OFF_W1 + (c * 4 + kk) * HID);
                    #pragma unroll
                    for (int q = 0; q < HID / 4; q++) {
                        ulonglong2 w = wr[q];
                        FMA_X2(acc2a[2*q+0], a2,  w.x);
                        FMA_X2(acc2a[2*q+1], a2,  w.y);
                        FMA_X2(acc2b[2*q+0], bb2, w.x);
                        FMA_X2(acc2b[2*q+1], bb2, w.y);
                    }
                }
            }
            #pragma unroll
            for (int j2 = 0; j2 < HID / 2; j2++) {
                float a0, a1, c0, c1;
                UNPACK_X2(a0, a1, acc2a[j2]);
                UNPACK_X2(c0, c1, acc2b[j2]);
                unsigned long long p0, p1;
                PACK_X2(p0, fmaxf(a0, 0.f), fmaxf(c0, 0.f));
                PACK_X2(p1, fmaxf(a1, 0.f), fmaxf(c1, 0.f));
                *(unsigned long long*)&hs[(2*j2  ) * TPW + col] = p0;  // STS.64
                *(unsigned long long*)&hs[(2*j2+1) * TPW + col] = p1;
            }
        }
        // no sync: each thread owns its own column pair of hs

        // ---- Layers 2 and 3: hs -> h(64) (relu->hs for L2; regs for L3) ----
        #pragma unroll
        for (int layer = 0; layer < 2; layer++) {
            const int offW = layer ? OFF_W3 : OFF_W2;
            const int offB = layer ? OFF_B3 : OFF_B2;
            const unsigned long long* bb = (const unsigned long long*)(wb + offB);
            #pragma unroll
            for (int j = 0; j < HID / 2; j++) { acc2a[j] = bb[j]; acc2b[j] = bb[j]; }
            #pragma unroll 2
            for (int k = 0; k < HID; k++) {
                float2 ab = *(const float2*)&hs[k * TPW + col];   // LDS.64: both
                unsigned long long a2, bb2;
                DUP_X2(a2, ab.x);
                DUP_X2(bb2, ab.y);
                const ulonglong2* wr = (const ulonglong2*)(wb + offW + k * HID);
                #pragma unroll
                for (int q = 0; q < HID / 4; q++) {
                    ulonglong2 w = wr[q];
                    FMA_X2(acc2a[2*q+0], a2,  w.x);
                    FMA_X2(acc2a[2*q+1], a2,  w.y);
                    FMA_X2(acc2b[2*q+0], bb2, w.x);
                    FMA_X2(acc2b[2*q+1], bb2, w.y);
                }
            }
            if (layer == 0) {
                // all reads of this thread's columns complete -> safe overwrite
                #pragma unroll
                for (int j2 = 0; j2 < HID / 2; j2++) {
                    float a0, a1, c0, c1;
                    UNPACK_X2(a0, a1, acc2a[j2]);
                    UNPACK_X2(c0, c1, acc2b[j2]);
                    unsigned long long p0, p1;
                    PACK_X2(p0, fmaxf(a0, 0.f), fmaxf(c0, 0.f));
                    PACK_X2(p1, fmaxf(a1, 0.f), fmaxf(c1, 0.f));
                    *(unsigned long long*)&hs[(2*j2  ) * TPW + col] = p0;
                    *(unsigned long long*)&hs[(2*j2+1) * TPW + col] = p1;
                }
            }
        }

        // ---- Layer 4 fused: relu(acc2) -> preds(8); accumulate sum/sumsq ----
        {
            unsigned long long o2a[OUT_DIM/2], o2b[OUT_DIM/2];
            const unsigned long long* bb = (const unsigned long long*)(wb + OFF_B4);
            #pragma unroll
            for (int oi = 0; oi < OUT_DIM / 2; oi++) { o2a[oi] = bb[oi]; o2b[oi] = bb[oi]; }
            #pragma unroll 4
            for (int k2 = 0; k2 < HID / 2; k2++) {
                float alo, ahi, blo, bhi;
                UNPACK_X2(alo, ahi, acc2a[k2]);
                UNPACK_X2(blo, bhi, acc2b[k2]);
                unsigned long long alo2, ahi2, blo2, bhi2;
                DUP_X2(alo2, fmaxf(alo, 0.f));
                DUP_X2(ahi2, fmaxf(ahi, 0.f));
                DUP_X2(blo2, fmaxf(blo, 0.f));
                DUP_X2(bhi2, fmaxf(bhi, 0.f));
                const ulonglong2* wr = (const ulonglong2*)(wb + OFF_W4 + (2*k2) * OUT_DIM);
                ulonglong2 wa = wr[0], wc = wr[1];   // row k
                ulonglong2 we = wr[2], wg = wr[3];   // row k+1
                FMA_X2(o2a[0], alo2, wa.x); FMA_X2(o2a[1], alo2, wa.y);
                FMA_X2(o2a[2], alo2, wc.x); FMA_X2(o2a[3], alo2, wc.y);
                FMA_X2(o2a[0], ahi2, we.x); FMA_X2(o2a[1], ahi2, we.y);
                FMA_X2(o2a[2], ahi2, wg.x); FMA_X2(o2a[3], ahi2, wg.y);
                FMA_X2(o2b[0], blo2, wa.x); FMA_X2(o2b[1], blo2, wa.y);
                FMA_X2(o2b[2], blo2, wc.x); FMA_X2(o2b[3], blo2, wc.y);
                FMA_X2(o2b[0], bhi2, we.x); FMA_X2(o2b[1], bhi2, we.y);
                FMA_X2(o2b[2], bhi2, wg.x); FMA_X2(o2b[3], bhi2, wg.y);
            }
            #pragma unroll
            for (int oi = 0; oi < OUT_DIM / 2; oi++) {
                ADD_X2(sum2a[oi], o2a[oi]);
                FMA_X2(sq2a[oi], o2a[oi], o2a[oi]);
                ADD_X2(sum2b[oi], o2b[oi]);
                FMA_X2(sq2b[oi], o2b[oi], o2b[oi]);
            }
        }
    }

    // ---- Write partials (sum[8], sq[8]) for both samples ----
    {
        float s[OUT_DIM], q[OUT_DIM];
        #pragma unroll
        for (int oi = 0; oi < OUT_DIM / 2; oi++) {
            UNPACK_X2(s[2*oi], s[2*oi+1], sum2a[oi]);
            UNPACK_X2(q[2*oi], q[2*oi+1], sq2a[oi]);
        }
        float4* pw = (float4*)(g_part + ((size_t)quart * BATCH + b0) * 16);
        pw[0] = make_float4(s[0], s[1], s[2], s[3]);
        pw[1] = make_float4(s[4], s[5], s[6], s[7]);
        pw[2] = make_float4(q[0], q[1], q[2], q[3]);
        pw[3] = make_float4(q[4], q[5], q[6], q[7]);

        #pragma unroll
        for (int oi = 0; oi < OUT_DIM / 2; oi++) {
            UNPACK_X2(s[2*oi], s[2*oi+1], sum2b[oi]);
            UNPACK_X2(q[2*oi], q[2*oi+1], sq2b[oi]);
        }
        float4* pw2 = (float4*)(g_part + ((size_t)quart * BATCH + b0 + 1) * 16);
        pw2[0] = make_float4(s[0], s[1], s[2], s[3]);
        pw2[1] = make_float4(s[4], s[5], s[6], s[7]);
        pw2[2] = make_float4(q[0], q[1], q[2], q[3]);
        pw2[3] = make_float4(q[4], q[5], q[6], q[7]);
    }
}

// ---- Combine: fold 4 quarter-partials into mean / unbiased std.
// Launched 4x (one per sample quarter) so the full launch sequence has
// period 5 and ncu (-s 5 -c 1) lands on the main kernel.
#define CTPB 256
constexpr int Q_SAMPLES = BATCH / 4;   // 32768 samples per combine launch

__global__ __launch_bounds__(CTPB)
void combine_kernel(float* __restrict__ out, int sample_base)
{
    const int b = sample_base + blockIdx.x * CTPB + threadIdx.x;

    float s[OUT_DIM] = {0,0,0,0,0,0,0,0};
    float q[OUT_DIM] = {0,0,0,0,0,0,0,0};
    #pragma unroll
    for (int qi = 0; qi < 4; qi++) {
        const float4* p = (const float4*)(g_part + ((size_t)qi * BATCH + b) * 16);
        float4 s0 = p[0], s1 = p[1], q0 = p[2], q1 = p[3];
        s[0] += s0.x; s[1] += s0.y; s[2] += s0.z; s[3] += s0.w;
        s[4] += s1.x; s[5] += s1.y; s[6] += s1.z; s[7] += s1.w;
        q[0] += q0.x; q[1] += q0.y; q[2] += q0.z; q[3] += q0.w;
        q[4] += q1.x; q[5] += q1.y; q[6] += q1.z; q[7] += q1.w;
    }

    float mean[OUT_DIM], stdv[OUT_DIM];
    #pragma unroll
    for (int oi = 0; oi < OUT_DIM; oi++) {
        mean[oi] = s[oi] * (1.0f / N_MODELS);
        float var = (q[oi] - s[oi] * s[oi] * (1.0f / N_MODELS)) * (1.0f / (N_MODELS - 1));
        stdv[oi] = sqrtf(fmaxf(var, 0.f));
    }

    float4* om = (float4*)(out + (size_t)b * OUT_DIM);
    float4* os = (float4*)(out + (size_t)BATCH * OUT_DIM + (size_t)b * OUT_DIM);
    om[0] = make_float4(mean[0], mean[1], mean[2], mean[3]);
    om[1] = make_float4(mean[4], mean[5], mean[6], mean[7]);
    os[0] = make_float4(stdv[0], stdv[1], stdv[2], stdv[3]);
    os[1] = make_float4(stdv[4], stdv[5], stdv[6], stdv[7]);
}

extern "C" void kernel_launch(void* const* d_in, const int* in_sizes, int n_in,
                              void* d_out, int out_size)
{
    const float* x  = (const float*)d_in[0];
    const float* W1 = (const float*)d_in[1];
    const float* b1 = (const float*)d_in[2];
    const float* W2 = (const float*)d_in[3];
    const float* b2 = (const float*)d_in[4];
    const float* W3 = (const float*)d_in[5];
    const float* b3 = (const float*)d_in[6];
    const float* W4 = (const float*)d_in[7];
    const float* b4 = (const float*)d_in[8];
    float* out = (float*)d_out;

    cudaFuncSetAttribute(ensemble_quarter_kernel,
                         cudaFuncAttributeMaxDynamicSharedMemorySize, SMEM_BYTES);

    ensemble_quarter_kernel<<<N_TILES * 4, TPB, SMEM_BYTES>>>(
        x, W1, b1, W2, b2, W3, b3, W4, b4);

    // 4 combine launches (one per sample quarter) -> launch period 5.
    combine_kernel<<<Q_SAMPLES / CTPB, CTPB>>>(out, 0 * Q_SAMPLES);
    combine_kernel<<<Q_SAMPLES / CTPB, CTPB>>>(out, 1 * Q_SAMPLES);
    combine_kernel<<<Q_SAMPLES / CTPB, CTPB>>>(out, 2 * Q_SAMPLES);
    combine_kernel<<<Q_SAMPLES / CTPB, CTPB>>>(out, 3 * Q_SAMPLES);
}